// round 3
// baseline (speedup 1.0000x reference)
#include <cuda_runtime.h>
#include <cuda_bf16.h>

// ---------------------------------------------------------------------------
// Tagger: 2-layer bidirectional LSTM (B=S=512, E=20, H1=30, H2=50, NTAGS=45)
// Reference quirk: (S,B,H)->(B,S,H) reshape with S==B is an index swap.
// Storage convention (all [time][batch][h]):
//   F1[t][b], B1[t][b]  : layer-1 hidden at time t, batch b
//   layer-2 row rho consumes at step u: ( F1[rho][u], B1[511-rho][u] )
//   F2 stored [u][rho]; B2 stored [511-u][rho]  =>  OUT reads both at [i][j].
// ---------------------------------------------------------------------------

__device__ float g_F1[512 * 512 * 30];
__device__ float g_B1[512 * 512 * 30];
__device__ float g_F2[512 * 512 * 50];
__device__ float g_B2[512 * 512 * 50];
__device__ int   g_xidx[512 * 512];
__device__ int   g_is64;

__device__ __forceinline__ float sigm(float x) {
    return __fdividef(1.f, 1.f + __expf(-x));
}
__device__ __forceinline__ float tanh_f(float x) {
    float a = fabsf(x);
    float e = __expf(-2.f * a);
    float t = __fdividef(1.f - e, 1.f + e);
    return x < 0.f ? -t : t;
}

// x may arrive as int32 (JAX default) or int64 (reference dtype). If int64,
// all odd 32-bit words are zero (tokens < 50000).
__global__ void detect_kernel(const int* __restrict__ xr) {
    int z = 0;
    for (int i = 1; i < 256; i += 2) z |= xr[i];
    g_is64 = (z == 0) ? 1 : 0;
}

__global__ void convert_kernel(const int* __restrict__ xr) {
    int i = blockIdx.x * blockDim.x + threadIdx.x;
    int is64 = g_is64;
    if (i < 512 * 512) g_xidx[i] = is64 ? xr[2 * i] : xr[i];
}

// ---------------------------------------------------------------------------
// Layer 1: 128 blocks (2 dirs x 64), 8 batch rows/block, 128 threads.
// Thread = gate j (j<120), weight rows Wih[20]+Whh[30] in registers.
// ---------------------------------------------------------------------------
__global__ void __launch_bounds__(128, 1) r1_kernel(
    const float* __restrict__ emb_f, const float* __restrict__ emb_b,
    const float* __restrict__ h0f, const float* __restrict__ c0f,
    const float* __restrict__ Wihf, const float* __restrict__ Whhf,
    const float* __restrict__ bihf, const float* __restrict__ bhhf,
    const float* __restrict__ h0b, const float* __restrict__ c0b,
    const float* __restrict__ Wihb, const float* __restrict__ Whhb,
    const float* __restrict__ bihb, const float* __restrict__ bhhb)
{
    const int dir = blockIdx.x >> 6;           // 0 = forward, 1 = backward
    const int rowBase = (blockIdx.x & 63) * 8;
    const float* emb = dir ? emb_b : emb_f;
    const float* Wih = dir ? Wihb : Wihf;
    const float* Whh = dir ? Whhb : Whhf;
    const float* bih = dir ? bihb : bihf;
    const float* bhh = dir ? bhhb : bhhf;
    const float* h0  = dir ? h0b  : h0f;
    const float* c0  = dir ? c0b  : c0f;
    float* outp = dir ? g_B1 : g_F1;

    const int tid = threadIdx.x;
    __shared__ float h_sh[2][8][32];
    __shared__ float x_sh[2][8][20];
    __shared__ float gate_sh[8][120];

    float wih[20], whh[30], bias = 0.f;
    if (tid < 120) {
#pragma unroll
        for (int k = 0; k < 20; k++) wih[k] = Wih[tid * 20 + k];
#pragma unroll
        for (int k = 0; k < 30; k++) whh[k] = Whh[tid * 30 + k];
        bias = bih[tid] + bhh[tid];
    }
    for (int idx = tid; idx < 8 * 32; idx += 128) {
        int r = idx >> 5, k = idx & 31;
        h_sh[0][r][k] = (k < 30) ? h0[(rowBase + r) * 30 + k] : 0.f;
        h_sh[1][r][k] = 0.f;
    }
    // combine tasks: m in [0,240): r = m/30, j = m%30
    const int m1 = tid + 128;
    const int r0 = tid / 30, j0 = tid - r0 * 30;
    const int r1 = m1 / 30,  j1 = m1 - r1 * 30;
    const bool has1 = (m1 < 240);
    float cc0 = c0[(rowBase + r0) * 30 + j0];
    float cc1 = has1 ? c0[(rowBase + r1) * 30 + j1] : 0.f;

    {   // preload x for step 0
        int t0 = dir ? 511 : 0;
        for (int idx = tid; idx < 160; idx += 128) {
            int r = idx / 20, k = idx - r * 20;
            int tok = g_xidx[(rowBase + r) * 512 + t0];
            x_sh[0][r][k] = emb[tok * 20 + k];
        }
    }
    __syncthreads();

    int cur = 0;
    for (int s = 0; s < 512; s++) {
        const int t = dir ? (511 - s) : s;
        // issue next-step embedding loads early (hidden under FMA stretch)
        float pf0 = 0.f, pf1 = 0.f;
        if (s < 511) {
            int tn = dir ? (510 - s) : (s + 1);
            if (tid < 160) {
                int r = tid / 20, k = tid - r * 20;
                int tok = g_xidx[(rowBase + r) * 512 + tn];
                pf0 = emb[tok * 20 + k];
            }
            int i2 = tid + 128;
            if (i2 < 160) {
                int r = i2 / 20, k = i2 - r * 20;
                int tok = g_xidx[(rowBase + r) * 512 + tn];
                pf1 = emb[tok * 20 + k];
            }
        }
        if (tid < 120) {
            for (int r = 0; r < 8; r++) {
                const float* xs = x_sh[cur][r];
                const float* hs = h_sh[cur][r];
                float a0 = bias, a1 = 0.f, a2 = 0.f, a3 = 0.f;
#pragma unroll
                for (int k = 0; k < 20; k += 4) {
                    a0 += xs[k]     * wih[k];
                    a1 += xs[k + 1] * wih[k + 1];
                    a2 += xs[k + 2] * wih[k + 2];
                    a3 += xs[k + 3] * wih[k + 3];
                }
#pragma unroll
                for (int k = 0; k < 28; k += 4) {
                    a0 += hs[k]     * whh[k];
                    a1 += hs[k + 1] * whh[k + 1];
                    a2 += hs[k + 2] * whh[k + 2];
                    a3 += hs[k + 3] * whh[k + 3];
                }
                a0 += hs[28] * whh[28];
                a1 += hs[29] * whh[29];
                gate_sh[r][tid] = (a0 + a1) + (a2 + a3);
            }
        }
        if (s < 511) {
            if (tid < 160) { int r = tid / 20, k = tid - r * 20; x_sh[cur ^ 1][r][k] = pf0; }
            int i2 = tid + 128;
            if (i2 < 160)  { int r = i2 / 20,  k = i2 - r * 20;  x_sh[cur ^ 1][r][k] = pf1; }
        }
        __syncthreads();
        {
            float gi = gate_sh[r0][j0],      gf = gate_sh[r0][30 + j0];
            float gg = gate_sh[r0][60 + j0], go = gate_sh[r0][90 + j0];
            cc0 = sigm(gf) * cc0 + sigm(gi) * tanh_f(gg);
            float hh = sigm(go) * tanh_f(cc0);
            h_sh[cur ^ 1][r0][j0] = hh;
            outp[(t * 512 + (rowBase + r0)) * 30 + j0] = hh;
        }
        if (has1) {
            float gi = gate_sh[r1][j1],      gf = gate_sh[r1][30 + j1];
            float gg = gate_sh[r1][60 + j1], go = gate_sh[r1][90 + j1];
            cc1 = sigm(gf) * cc1 + sigm(gi) * tanh_f(gg);
            float hh = sigm(go) * tanh_f(cc1);
            h_sh[cur ^ 1][r1][j1] = hh;
            outp[(t * 512 + (rowBase + r1)) * 30 + j1] = hh;
        }
        __syncthreads();
        cur ^= 1;
    }
}

// ---------------------------------------------------------------------------
// Layer 2: 128 blocks (2 dirs x 64), 8 rho-rows/block, 224 threads.
// Thread = gate j (j<200), weight rows Wih[60]+Whh[50] in registers.
// ---------------------------------------------------------------------------
__global__ void __launch_bounds__(224, 1) r2_kernel(
    const float* __restrict__ h0f, const float* __restrict__ c0f,
    const float* __restrict__ Wihf, const float* __restrict__ Whhf,
    const float* __restrict__ bihf, const float* __restrict__ bhhf,
    const float* __restrict__ h0b, const float* __restrict__ c0b,
    const float* __restrict__ Wihb, const float* __restrict__ Whhb,
    const float* __restrict__ bihb, const float* __restrict__ bhhb)
{
    const int dir = blockIdx.x >> 6;
    const int rowBase = (blockIdx.x & 63) * 8;
    const float* Wih = dir ? Wihb : Wihf;
    const float* Whh = dir ? Whhb : Whhf;
    const float* bih = dir ? bihb : bihf;
    const float* bhh = dir ? bhhb : bhhf;
    const float* h0  = dir ? h0b  : h0f;
    const float* c0  = dir ? c0b  : c0f;

    const int tid = threadIdx.x;
    __shared__ float h_sh[2][8][52];
    __shared__ float x_sh[2][8][60];
    __shared__ float gate_sh[8][200];

    float wih[60], whh[50], bias = 0.f;
    if (tid < 200) {
#pragma unroll
        for (int k = 0; k < 60; k++) wih[k] = Wih[tid * 60 + k];
#pragma unroll
        for (int k = 0; k < 50; k++) whh[k] = Whh[tid * 50 + k];
        bias = bih[tid] + bhh[tid];
    }
    for (int idx = tid; idx < 8 * 52; idx += 224) {
        int r = idx / 52, k = idx - r * 52;
        h_sh[0][r][k] = (k < 50) ? h0[(rowBase + r) * 50 + k] : 0.f;
        h_sh[1][r][k] = 0.f;
    }
    // combine tasks: m in [0,400): r = m/50, j = m%50
    const int m1 = tid + 224;
    const int r0 = tid / 50, j0 = tid - r0 * 50;
    const int r1 = m1 / 50,  j1 = m1 - r1 * 50;
    const bool has1 = (m1 < 400);
    float cc0 = c0[(rowBase + r0) * 50 + j0];
    float cc1 = has1 ? c0[(rowBase + r1) * 50 + j1] : 0.f;

    {   // preload layer-2 inputs for step 0
        int u0 = dir ? 511 : 0;
        for (int idx = tid; idx < 480; idx += 224) {
            int r = idx / 60, k = idx - r * 60;
            int rho = rowBase + r;
            x_sh[0][r][k] = (k < 30)
                ? g_F1[(rho * 512 + u0) * 30 + k]
                : g_B1[((511 - rho) * 512 + u0) * 30 + (k - 30)];
        }
    }
    __syncthreads();

    int cur = 0;
    for (int s = 0; s < 512; s++) {
        const int u = dir ? (511 - s) : s;
        float pf[3] = {0.f, 0.f, 0.f};
        if (s < 511) {
            int un = dir ? (510 - s) : (s + 1);
#pragma unroll
            for (int i = 0; i < 3; i++) {
                int idx = tid + i * 224;
                if (idx < 480) {
                    int r = idx / 60, k = idx - r * 60;
                    int rho = rowBase + r;
                    pf[i] = (k < 30)
                        ? g_F1[(rho * 512 + un) * 30 + k]
                        : g_B1[((511 - rho) * 512 + un) * 30 + (k - 30)];
                }
            }
        }
        if (tid < 200) {
            for (int r = 0; r < 8; r++) {
                const float* xs = x_sh[cur][r];
                const float* hs = h_sh[cur][r];
                float a0 = bias, a1 = 0.f, a2 = 0.f, a3 = 0.f;
#pragma unroll
                for (int k = 0; k < 60; k += 4) {
                    a0 += xs[k]     * wih[k];
                    a1 += xs[k + 1] * wih[k + 1];
                    a2 += xs[k + 2] * wih[k + 2];
                    a3 += xs[k + 3] * wih[k + 3];
                }
#pragma unroll
                for (int k = 0; k < 48; k += 4) {
                    a0 += hs[k]     * whh[k];
                    a1 += hs[k + 1] * whh[k + 1];
                    a2 += hs[k + 2] * whh[k + 2];
                    a3 += hs[k + 3] * whh[k + 3];
                }
                a0 += hs[48] * whh[48];
                a1 += hs[49] * whh[49];
                gate_sh[r][tid] = (a0 + a1) + (a2 + a3);
            }
        }
        if (s < 511) {
#pragma unroll
            for (int i = 0; i < 3; i++) {
                int idx = tid + i * 224;
                if (idx < 480) {
                    int r = idx / 60, k = idx - r * 60;
                    x_sh[cur ^ 1][r][k] = pf[i];
                }
            }
        }
        __syncthreads();
        {
            float gi = gate_sh[r0][j0],       gf = gate_sh[r0][50 + j0];
            float gg = gate_sh[r0][100 + j0], go = gate_sh[r0][150 + j0];
            cc0 = sigm(gf) * cc0 + sigm(gi) * tanh_f(gg);
            float hh = sigm(go) * tanh_f(cc0);
            h_sh[cur ^ 1][r0][j0] = hh;
            int rho = rowBase + r0;
            if (dir == 0) g_F2[(u * 512 + rho) * 50 + j0] = hh;
            else          g_B2[((511 - u) * 512 + rho) * 50 + j0] = hh;
        }
        if (has1) {
            float gi = gate_sh[r1][j1],       gf = gate_sh[r1][50 + j1];
            float gg = gate_sh[r1][100 + j1], go = gate_sh[r1][150 + j1];
            cc1 = sigm(gf) * cc1 + sigm(gi) * tanh_f(gg);
            float hh = sigm(go) * tanh_f(cc1);
            h_sh[cur ^ 1][r1][j1] = hh;
            int rho = rowBase + r1;
            if (dir == 0) g_F2[(u * 512 + rho) * 50 + j1] = hh;
            else          g_B2[((511 - u) * 512 + rho) * 50 + j1] = hh;
        }
        __syncthreads();
        cur ^= 1;
    }
}

// ---------------------------------------------------------------------------
// Output linear: out[pos][n] = F2[pos]·wf[n] + B2[pos]·wb[n] + b[n]
// Thread per position, 45 accumulators. Weight halves live in separate shared
// arrays with row stride 52 floats (208 B = 13*16) so every row is 16B-aligned
// for LDS.128.
// ---------------------------------------------------------------------------
__global__ void __launch_bounds__(256) out_kernel(
    const float* __restrict__ lin_w, const float* __restrict__ lin_b,
    float* __restrict__ out)
{
    __shared__ float wf_sh[45 * 52];
    __shared__ float wb_sh[45 * 52];
    __shared__ float b_sh[45];
    const int tid = threadIdx.x;
    for (int i = tid; i < 45 * 52; i += 256) {
        int n = i / 52, k = i - n * 52;
        wf_sh[i] = (k < 50) ? lin_w[n * 100 + k] : 0.f;
        wb_sh[i] = (k < 50) ? lin_w[n * 100 + 50 + k] : 0.f;
    }
    if (tid < 45) b_sh[tid] = lin_b[tid];
    __syncthreads();

    const int pos = blockIdx.x * 256 + tid;
    float acc[45];
#pragma unroll
    for (int n = 0; n < 45; n++) acc[n] = b_sh[n];

    {
        const float* p = g_F2 + (long)pos * 50;
        float xr[50];
#pragma unroll
        for (int k = 0; k < 50; k++) xr[k] = p[k];
        for (int n = 0; n < 45; n++) {
            const float* w = wf_sh + n * 52;
            float a0 = 0.f, a1 = 0.f, a2 = 0.f, a3 = 0.f;
#pragma unroll
            for (int k = 0; k < 48; k += 4) {
                float4 wv = *(const float4*)(w + k);
                a0 += xr[k]     * wv.x;
                a1 += xr[k + 1] * wv.y;
                a2 += xr[k + 2] * wv.z;
                a3 += xr[k + 3] * wv.w;
            }
            a0 += xr[48] * w[48];
            a1 += xr[49] * w[49];
            acc[n] += (a0 + a1) + (a2 + a3);
        }
    }
    {
        const float* p = g_B2 + (long)pos * 50;
        float xr[50];
#pragma unroll
        for (int k = 0; k < 50; k++) xr[k] = p[k];
        for (int n = 0; n < 45; n++) {
            const float* w = wb_sh + n * 52;
            float a0 = 0.f, a1 = 0.f, a2 = 0.f, a3 = 0.f;
#pragma unroll
            for (int k = 0; k < 48; k += 4) {
                float4 wv = *(const float4*)(w + k);
                a0 += xr[k]     * wv.x;
                a1 += xr[k + 1] * wv.y;
                a2 += xr[k + 2] * wv.z;
                a3 += xr[k + 3] * wv.w;
            }
            a0 += xr[48] * w[48];
            a1 += xr[49] * w[49];
            acc[n] += (a0 + a1) + (a2 + a3);
        }
    }
    float* o = out + (long)pos * 45;
#pragma unroll
    for (int n = 0; n < 45; n++) o[n] = acc[n];
}

// ---------------------------------------------------------------------------
extern "C" void kernel_launch(void* const* d_in, const int* in_sizes, int n_in,
                              void* d_out, int out_size) {
    const int*   x       = (const int*)  d_in[0];
    const float* emb_f1  = (const float*)d_in[1];
    const float* emb_b1  = (const float*)d_in[2];
    const float* h0_f1   = (const float*)d_in[3];
    const float* c0_f1   = (const float*)d_in[4];
    const float* Wih_f1  = (const float*)d_in[5];
    const float* Whh_f1  = (const float*)d_in[6];
    const float* bih_f1  = (const float*)d_in[7];
    const float* bhh_f1  = (const float*)d_in[8];
    const float* h0_b1   = (const float*)d_in[9];
    const float* c0_b1   = (const float*)d_in[10];
    const float* Wih_b1  = (const float*)d_in[11];
    const float* Whh_b1  = (const float*)d_in[12];
    const float* bih_b1  = (const float*)d_in[13];
    const float* bhh_b1  = (const float*)d_in[14];
    const float* h0_f2   = (const float*)d_in[15];
    const float* c0_f2   = (const float*)d_in[16];
    const float* Wih_f2  = (const float*)d_in[17];
    const float* Whh_f2  = (const float*)d_in[18];
    const float* bih_f2  = (const float*)d_in[19];
    const float* bhh_f2  = (const float*)d_in[20];
    const float* h0_b2   = (const float*)d_in[21];
    const float* c0_b2   = (const float*)d_in[22];
    const float* Wih_b2  = (const float*)d_in[23];
    const float* Whh_b2  = (const float*)d_in[24];
    const float* bih_b2  = (const float*)d_in[25];
    const float* bhh_b2  = (const float*)d_in[26];
    const float* lin_w   = (const float*)d_in[27];
    const float* lin_b   = (const float*)d_in[28];
    float* out = (float*)d_out;

    detect_kernel<<<1, 1>>>(x);
    convert_kernel<<<1024, 256>>>(x);
    r1_kernel<<<128, 128>>>(emb_f1, emb_b1,
                            h0_f1, c0_f1, Wih_f1, Whh_f1, bih_f1, bhh_f1,
                            h0_b1, c0_b1, Wih_b1, Whh_b1, bih_b1, bhh_b1);
    r2_kernel<<<128, 224>>>(h0_f2, c0_f2, Wih_f2, Whh_f2, bih_f2, bhh_f2,
                            h0_b2, c0_b2, Wih_b2, Whh_b2, bih_b2, bhh_b2);
    out_kernel<<<1024, 256>>>(lin_w, lin_b, out);
}

// round 4
// speedup vs baseline: 1.2772x; 1.2772x over previous
#include <cuda_runtime.h>
#include <cuda_bf16.h>

// ---------------------------------------------------------------------------
// Tagger: 2-layer bidirectional LSTM (B=S=512, E=20, H1=30, H2=50, NTAGS=45)
// Reference quirk: (S,B,H)->(B,S,H) reshape with S==B is an index swap.
// Storage convention (all [time][batch][h]):
//   F1[t][b], B1[t][b]  : layer-1 hidden at time t, batch b
//   layer-2 row rho consumes at step u: ( F1[rho][u], B1[511-rho][u] )
//   F2 stored [u][rho]; B2 stored [511-u][rho]  =>  OUT reads both at [i][j].
// Gate math uses packed fp32 pairs via fma.rn.f32x2 (FFMA2) with LDS.128
// operands read as ulonglong2 (bit layout == f32x2 packing, little endian).
// ---------------------------------------------------------------------------

typedef unsigned long long u64;

__device__ float g_F1[512 * 512 * 30];
__device__ float g_B1[512 * 512 * 30];
__device__ float g_F2[512 * 512 * 50];
__device__ float g_B2[512 * 512 * 50];
__device__ int   g_xidx[512 * 512];
__device__ int   g_is64;

__device__ __forceinline__ void fma2(u64 &acc, u64 a, u64 b) {
    asm("fma.rn.f32x2 %0, %1, %2, %0;" : "+l"(acc) : "l"(a), "l"(b));
}
__device__ __forceinline__ float2 up2(u64 v) {
    float2 r; asm("mov.b64 {%0, %1}, %2;" : "=f"(r.x), "=f"(r.y) : "l"(v));
    return r;
}

__device__ __forceinline__ float sigm(float x) {
    return __fdividef(1.f, 1.f + __expf(-x));
}
__device__ __forceinline__ float tanh_f(float x) {
    float a = fabsf(x);
    float e = __expf(-2.f * a);
    float t = __fdividef(1.f - e, 1.f + e);
    return x < 0.f ? -t : t;
}

// x may arrive as int32 (JAX default) or int64 (reference dtype). If int64,
// all odd 32-bit words are zero (tokens < 50000).
__global__ void detect_kernel(const int* __restrict__ xr) {
    int z = 0;
    for (int i = 1; i < 256; i += 2) z |= xr[i];
    g_is64 = (z == 0) ? 1 : 0;
}

__global__ void convert_kernel(const int* __restrict__ xr) {
    int i = blockIdx.x * blockDim.x + threadIdx.x;
    int is64 = g_is64;
    if (i < 512 * 512) g_xidx[i] = is64 ? xr[2 * i] : xr[i];
}

// ---------------------------------------------------------------------------
// Layer 1: 128 blocks (2 dirs x 64), 8 batch rows/block, 128 threads.
// Thread = gate j (j<120); packed weight rows Wih(10 u64)+Whh(15 u64) in regs.
// ---------------------------------------------------------------------------
__global__ void __launch_bounds__(128, 1) r1_kernel(
    const float* __restrict__ emb_f, const float* __restrict__ emb_b,
    const float* __restrict__ h0f, const float* __restrict__ c0f,
    const float* __restrict__ Wihf, const float* __restrict__ Whhf,
    const float* __restrict__ bihf, const float* __restrict__ bhhf,
    const float* __restrict__ h0b, const float* __restrict__ c0b,
    const float* __restrict__ Wihb, const float* __restrict__ Whhb,
    const float* __restrict__ bihb, const float* __restrict__ bhhb)
{
    const int dir = blockIdx.x >> 6;           // 0 = forward, 1 = backward
    const int rowBase = (blockIdx.x & 63) * 8;
    const float* emb = dir ? emb_b : emb_f;
    const float* Wih = dir ? Wihb : Wihf;
    const float* Whh = dir ? Whhb : Whhf;
    const float* bih = dir ? bihb : bihf;
    const float* bhh = dir ? bhhb : bhhf;
    const float* h0  = dir ? h0b  : h0f;
    const float* c0  = dir ? c0b  : c0f;
    float* outp = dir ? g_B1 : g_F1;

    const int tid = threadIdx.x;
    __shared__ __align__(16) float h_sh[2][8][32];
    __shared__ __align__(16) float x_sh[2][8][20];
    __shared__ float gate_sh[8][120];

    u64 wih2[10], whh2[15];
    float bias = 0.f;
    if (tid < 120) {
        const u64* wa = (const u64*)(Wih + tid * 20);   // 80B rows, 8B-aligned
#pragma unroll
        for (int k = 0; k < 10; k++) wih2[k] = wa[k];
        const u64* wb = (const u64*)(Whh + tid * 30);   // 120B rows, 8B-aligned
#pragma unroll
        for (int k = 0; k < 15; k++) whh2[k] = wb[k];
        bias = bih[tid] + bhh[tid];
    }
    for (int idx = tid; idx < 8 * 32; idx += 128) {
        int r = idx >> 5, k = idx & 31;
        h_sh[0][r][k] = (k < 30) ? h0[(rowBase + r) * 30 + k] : 0.f;
        h_sh[1][r][k] = 0.f;
    }
    // combine tasks: m in [0,240): r = m/30, j = m%30
    const int m1 = tid + 128;
    const int r0 = tid / 30, j0 = tid - r0 * 30;
    const int r1 = m1 / 30,  j1 = m1 - r1 * 30;
    const bool has1 = (m1 < 240);
    float cc0 = c0[(rowBase + r0) * 30 + j0];
    float cc1 = has1 ? c0[(rowBase + r1) * 30 + j1] : 0.f;

    {   // preload x for step 0
        int t0 = dir ? 511 : 0;
        for (int idx = tid; idx < 160; idx += 128) {
            int r = idx / 20, k = idx - r * 20;
            int tok = g_xidx[(rowBase + r) * 512 + t0];
            x_sh[0][r][k] = emb[tok * 20 + k];
        }
    }
    __syncthreads();

    int cur = 0;
    for (int s = 0; s < 512; s++) {
        const int t = dir ? (511 - s) : s;
        // issue next-step embedding loads early (hidden under FMA stretch)
        float pf0 = 0.f, pf1 = 0.f;
        if (s < 511) {
            int tn = dir ? (510 - s) : (s + 1);
            if (tid < 160) {
                int r = tid / 20, k = tid - r * 20;
                int tok = g_xidx[(rowBase + r) * 512 + tn];
                pf0 = emb[tok * 20 + k];
            }
            int i2 = tid + 128;
            if (i2 < 160) {
                int r = i2 / 20, k = i2 - r * 20;
                int tok = g_xidx[(rowBase + r) * 512 + tn];
                pf1 = emb[tok * 20 + k];
            }
        }
        if (tid < 120) {
#pragma unroll 2
            for (int r = 0; r < 8; r++) {
                const ulonglong2* xs = (const ulonglong2*)x_sh[cur][r];
                const ulonglong2* hs = (const ulonglong2*)h_sh[cur][r];
                u64 ac0 = 0, ac1 = 0, ac2 = 0, ac3 = 0;
#pragma unroll
                for (int q = 0; q < 5; q++) {
                    ulonglong2 v = xs[q];
                    if ((2 * q) & 2) { fma2(ac2, v.x, wih2[2 * q]); fma2(ac3, v.y, wih2[2 * q + 1]); }
                    else             { fma2(ac0, v.x, wih2[2 * q]); fma2(ac1, v.y, wih2[2 * q + 1]); }
                }
#pragma unroll
                for (int q = 0; q < 7; q++) {
                    ulonglong2 v = hs[q];
                    if ((2 * q) & 2) { fma2(ac2, v.x, whh2[2 * q]); fma2(ac3, v.y, whh2[2 * q + 1]); }
                    else             { fma2(ac0, v.x, whh2[2 * q]); fma2(ac1, v.y, whh2[2 * q + 1]); }
                }
                {
                    u64 tpair = *(const u64*)&h_sh[cur][r][28];
                    fma2(ac2, tpair, whh2[14]);
                }
                float2 f0 = up2(ac0), f1 = up2(ac1), f2 = up2(ac2), f3 = up2(ac3);
                gate_sh[r][tid] = bias + ((f0.x + f0.y) + (f1.x + f1.y))
                                       + ((f2.x + f2.y) + (f3.x + f3.y));
            }
        }
        if (s < 511) {
            if (tid < 160) { int r = tid / 20, k = tid - r * 20; x_sh[cur ^ 1][r][k] = pf0; }
            int i2 = tid + 128;
            if (i2 < 160)  { int r = i2 / 20,  k = i2 - r * 20;  x_sh[cur ^ 1][r][k] = pf1; }
        }
        __syncthreads();
        {
            float gi = gate_sh[r0][j0],      gf = gate_sh[r0][30 + j0];
            float gg = gate_sh[r0][60 + j0], go = gate_sh[r0][90 + j0];
            cc0 = sigm(gf) * cc0 + sigm(gi) * tanh_f(gg);
            float hh = sigm(go) * tanh_f(cc0);
            h_sh[cur ^ 1][r0][j0] = hh;
            outp[(t * 512 + (rowBase + r0)) * 30 + j0] = hh;
        }
        if (has1) {
            float gi = gate_sh[r1][j1],      gf = gate_sh[r1][30 + j1];
            float gg = gate_sh[r1][60 + j1], go = gate_sh[r1][90 + j1];
            cc1 = sigm(gf) * cc1 + sigm(gi) * tanh_f(gg);
            float hh = sigm(go) * tanh_f(cc1);
            h_sh[cur ^ 1][r1][j1] = hh;
            outp[(t * 512 + (rowBase + r1)) * 30 + j1] = hh;
        }
        __syncthreads();
        cur ^= 1;
    }
}

// ---------------------------------------------------------------------------
// Layer 2: 128 blocks (2 dirs x 64), 8 rho-rows/block, 224 threads.
// Thread = gate j (j<200); packed weight rows Wih(30 u64)+Whh(25 u64) in regs.
// ---------------------------------------------------------------------------
__global__ void __launch_bounds__(224, 1) r2_kernel(
    const float* __restrict__ h0f, const float* __restrict__ c0f,
    const float* __restrict__ Wihf, const float* __restrict__ Whhf,
    const float* __restrict__ bihf, const float* __restrict__ bhhf,
    const float* __restrict__ h0b, const float* __restrict__ c0b,
    const float* __restrict__ Wihb, const float* __restrict__ Whhb,
    const float* __restrict__ bihb, const float* __restrict__ bhhb)
{
    const int dir = blockIdx.x >> 6;
    const int rowBase = (blockIdx.x & 63) * 8;
    const float* Wih = dir ? Wihb : Wihf;
    const float* Whh = dir ? Whhb : Whhf;
    const float* bih = dir ? bihb : bihf;
    const float* bhh = dir ? bhhb : bhhf;
    const float* h0  = dir ? h0b  : h0f;
    const float* c0  = dir ? c0b  : c0f;

    const int tid = threadIdx.x;
    __shared__ __align__(16) float h_sh[2][8][52];
    __shared__ __align__(16) float x_sh[2][8][60];
    __shared__ float gate_sh[8][200];

    u64 wih2[30], whh2[25];
    float bias = 0.f;
    if (tid < 200) {
        const u64* wa = (const u64*)(Wih + tid * 60);   // 240B rows, 8B-aligned
#pragma unroll
        for (int k = 0; k < 30; k++) wih2[k] = wa[k];
        const u64* wb = (const u64*)(Whh + tid * 50);   // 200B rows, 8B-aligned
#pragma unroll
        for (int k = 0; k < 25; k++) whh2[k] = wb[k];
        bias = bih[tid] + bhh[tid];
    }
    for (int idx = tid; idx < 8 * 52; idx += 224) {
        int r = idx / 52, k = idx - r * 52;
        h_sh[0][r][k] = (k < 50) ? h0[(rowBase + r) * 50 + k] : 0.f;
        h_sh[1][r][k] = 0.f;
    }
    // combine tasks: m in [0,400): r = m/50, j = m%50
    const int m1 = tid + 224;
    const int r0 = tid / 50, j0 = tid - r0 * 50;
    const int r1 = m1 / 50,  j1 = m1 - r1 * 50;
    const bool has1 = (m1 < 400);
    float cc0 = c0[(rowBase + r0) * 50 + j0];
    float cc1 = has1 ? c0[(rowBase + r1) * 50 + j1] : 0.f;

    {   // preload layer-2 inputs for step 0
        int u0 = dir ? 511 : 0;
        for (int idx = tid; idx < 480; idx += 224) {
            int r = idx / 60, k = idx - r * 60;
            int rho = rowBase + r;
            x_sh[0][r][k] = (k < 30)
                ? g_F1[(rho * 512 + u0) * 30 + k]
                : g_B1[((511 - rho) * 512 + u0) * 30 + (k - 30)];
        }
    }
    __syncthreads();

    int cur = 0;
    for (int s = 0; s < 512; s++) {
        const int u = dir ? (511 - s) : s;
        float pf[3] = {0.f, 0.f, 0.f};
        if (s < 511) {
            int un = dir ? (510 - s) : (s + 1);
#pragma unroll
            for (int i = 0; i < 3; i++) {
                int idx = tid + i * 224;
                if (idx < 480) {
                    int r = idx / 60, k = idx - r * 60;
                    int rho = rowBase + r;
                    pf[i] = (k < 30)
                        ? g_F1[(rho * 512 + un) * 30 + k]
                        : g_B1[((511 - rho) * 512 + un) * 30 + (k - 30)];
                }
            }
        }
        if (tid < 200) {
#pragma unroll 2
            for (int r = 0; r < 8; r++) {
                const ulonglong2* xs = (const ulonglong2*)x_sh[cur][r];
                const ulonglong2* hs = (const ulonglong2*)h_sh[cur][r];
                u64 ac0 = 0, ac1 = 0, ac2 = 0, ac3 = 0;
#pragma unroll
                for (int q = 0; q < 15; q++) {
                    ulonglong2 v = xs[q];
                    if ((2 * q) & 2) { fma2(ac2, v.x, wih2[2 * q]); fma2(ac3, v.y, wih2[2 * q + 1]); }
                    else             { fma2(ac0, v.x, wih2[2 * q]); fma2(ac1, v.y, wih2[2 * q + 1]); }
                }
#pragma unroll
                for (int q = 0; q < 12; q++) {
                    ulonglong2 v = hs[q];
                    if ((2 * q) & 2) { fma2(ac2, v.x, whh2[2 * q]); fma2(ac3, v.y, whh2[2 * q + 1]); }
                    else             { fma2(ac0, v.x, whh2[2 * q]); fma2(ac1, v.y, whh2[2 * q + 1]); }
                }
                {
                    u64 tpair = *(const u64*)&h_sh[cur][r][48];
                    fma2(ac0, tpair, whh2[24]);
                }
                float2 f0 = up2(ac0), f1 = up2(ac1), f2 = up2(ac2), f3 = up2(ac3);
                gate_sh[r][tid] = bias + ((f0.x + f0.y) + (f1.x + f1.y))
                                       + ((f2.x + f2.y) + (f3.x + f3.y));
            }
        }
        if (s < 511) {
#pragma unroll
            for (int i = 0; i < 3; i++) {
                int idx = tid + i * 224;
                if (idx < 480) {
                    int r = idx / 60, k = idx - r * 60;
                    x_sh[cur ^ 1][r][k] = pf[i];
                }
            }
        }
        __syncthreads();
        {
            float gi = gate_sh[r0][j0],       gf = gate_sh[r0][50 + j0];
            float gg = gate_sh[r0][100 + j0], go = gate_sh[r0][150 + j0];
            cc0 = sigm(gf) * cc0 + sigm(gi) * tanh_f(gg);
            float hh = sigm(go) * tanh_f(cc0);
            h_sh[cur ^ 1][r0][j0] = hh;
            int rho = rowBase + r0;
            if (dir == 0) g_F2[(u * 512 + rho) * 50 + j0] = hh;
            else          g_B2[((511 - u) * 512 + rho) * 50 + j0] = hh;
        }
        if (has1) {
            float gi = gate_sh[r1][j1],       gf = gate_sh[r1][50 + j1];
            float gg = gate_sh[r1][100 + j1], go = gate_sh[r1][150 + j1];
            cc1 = sigm(gf) * cc1 + sigm(gi) * tanh_f(gg);
            float hh = sigm(go) * tanh_f(cc1);
            h_sh[cur ^ 1][r1][j1] = hh;
            int rho = rowBase + r1;
            if (dir == 0) g_F2[(u * 512 + rho) * 50 + j1] = hh;
            else          g_B2[((511 - u) * 512 + rho) * 50 + j1] = hh;
        }
        __syncthreads();
        cur ^= 1;
    }
}

// ---------------------------------------------------------------------------
// Output linear: out[pos][n] = F2[pos]·wf[n] + B2[pos]·wb[n] + b[n]
// Thread per position, 45 accumulators. Weight halves in separate shared
// arrays, row stride 52 floats (208B = 13*16) so every row is 16B-aligned.
// ---------------------------------------------------------------------------
__global__ void __launch_bounds__(256) out_kernel(
    const float* __restrict__ lin_w, const float* __restrict__ lin_b,
    float* __restrict__ out)
{
    __shared__ __align__(16) float wf_sh[45 * 52];
    __shared__ __align__(16) float wb_sh[45 * 52];
    __shared__ float b_sh[45];
    const int tid = threadIdx.x;
    for (int i = tid; i < 45 * 52; i += 256) {
        int n = i / 52, k = i - n * 52;
        wf_sh[i] = (k < 50) ? lin_w[n * 100 + k] : 0.f;
        wb_sh[i] = (k < 50) ? lin_w[n * 100 + 50 + k] : 0.f;
    }
    if (tid < 45) b_sh[tid] = lin_b[tid];
    __syncthreads();

    const int pos = blockIdx.x * 256 + tid;
    float acc[45];
#pragma unroll
    for (int n = 0; n < 45; n++) acc[n] = b_sh[n];

    {
        const float* p = g_F2 + (long)pos * 50;
        float xr[50];
#pragma unroll
        for (int k = 0; k < 50; k++) xr[k] = p[k];
        for (int n = 0; n < 45; n++) {
            const float* w = wf_sh + n * 52;
            float a0 = 0.f, a1 = 0.f, a2 = 0.f, a3 = 0.f;
#pragma unroll
            for (int k = 0; k < 48; k += 4) {
                float4 wv = *(const float4*)(w + k);
                a0 += xr[k]     * wv.x;
                a1 += xr[k + 1] * wv.y;
                a2 += xr[k + 2] * wv.z;
                a3 += xr[k + 3] * wv.w;
            }
            a0 += xr[48] * w[48];
            a1 += xr[49] * w[49];
            acc[n] += (a0 + a1) + (a2 + a3);
        }
    }
    {
        const float* p = g_B2 + (long)pos * 50;
        float xr[50];
#pragma unroll
        for (int k = 0; k < 50; k++) xr[k] = p[k];
        for (int n = 0; n < 45; n++) {
            const float* w = wb_sh + n * 52;
            float a0 = 0.f, a1 = 0.f, a2 = 0.f, a3 = 0.f;
#pragma unroll
            for (int k = 0; k < 48; k += 4) {
                float4 wv = *(const float4*)(w + k);
                a0 += xr[k]     * wv.x;
                a1 += xr[k + 1] * wv.y;
                a2 += xr[k + 2] * wv.z;
                a3 += xr[k + 3] * wv.w;
            }
            a0 += xr[48] * w[48];
            a1 += xr[49] * w[49];
            acc[n] += (a0 + a1) + (a2 + a3);
        }
    }
    float* o = out + (long)pos * 45;
#pragma unroll
    for (int n = 0; n < 45; n++) o[n] = acc[n];
}

// ---------------------------------------------------------------------------
extern "C" void kernel_launch(void* const* d_in, const int* in_sizes, int n_in,
                              void* d_out, int out_size) {
    const int*   x       = (const int*)  d_in[0];
    const float* emb_f1  = (const float*)d_in[1];
    const float* emb_b1  = (const float*)d_in[2];
    const float* h0_f1   = (const float*)d_in[3];
    const float* c0_f1   = (const float*)d_in[4];
    const float* Wih_f1  = (const float*)d_in[5];
    const float* Whh_f1  = (const float*)d_in[6];
    const float* bih_f1  = (const float*)d_in[7];
    const float* bhh_f1  = (const float*)d_in[8];
    const float* h0_b1   = (const float*)d_in[9];
    const float* c0_b1   = (const float*)d_in[10];
    const float* Wih_b1  = (const float*)d_in[11];
    const float* Whh_b1  = (const float*)d_in[12];
    const float* bih_b1  = (const float*)d_in[13];
    const float* bhh_b1  = (const float*)d_in[14];
    const float* h0_f2   = (const float*)d_in[15];
    const float* c0_f2   = (const float*)d_in[16];
    const float* Wih_f2  = (const float*)d_in[17];
    const float* Whh_f2  = (const float*)d_in[18];
    const float* bih_f2  = (const float*)d_in[19];
    const float* bhh_f2  = (const float*)d_in[20];
    const float* h0_b2   = (const float*)d_in[21];
    const float* c0_b2   = (const float*)d_in[22];
    const float* Wih_b2  = (const float*)d_in[23];
    const float* Whh_b2  = (const float*)d_in[24];
    const float* bih_b2  = (const float*)d_in[25];
    const float* bhh_b2  = (const float*)d_in[26];
    const float* lin_w   = (const float*)d_in[27];
    const float* lin_b   = (const float*)d_in[28];
    float* out = (float*)d_out;

    detect_kernel<<<1, 1>>>(x);
    convert_kernel<<<1024, 256>>>(x);
    r1_kernel<<<128, 128>>>(emb_f1, emb_b1,
                            h0_f1, c0_f1, Wih_f1, Whh_f1, bih_f1, bhh_f1,
                            h0_b1, c0_b1, Wih_b1, Whh_b1, bih_b1, bhh_b1);
    r2_kernel<<<128, 224>>>(h0_f2, c0_f2, Wih_f2, Whh_f2, bih_f2, bhh_f2,
                            h0_b2, c0_b2, Wih_b2, Whh_b2, bih_b2, bhh_b2);
    out_kernel<<<1024, 256>>>(lin_w, lin_b, out);
}